// round 15
// baseline (speedup 1.0000x reference)
#include <cuda_runtime.h>
#include <cuda_bf16.h>
#include <math.h>
#include <stdint.h>

#define BB   16
#define SSQ  256
#define DD   512
#define KCL  20
#define NTOK 4096
#define NZ   40960
#define NPB  2560
#define LOG_NORM_F (-0.91893853320467274178f)

typedef __nv_bfloat16 bf16;
typedef __nv_bfloat162 bf162;

// fp32 buffers
__device__ float g_qkv[NTOK*1536];
__device__ float g_o[NTOK*DD];
__device__ float g_hB[NTOK*DD];
__device__ float g_att[64*SSQ*SSQ];
__device__ float g_z[NZ*64];
__device__ float g_logqz[NZ];
__device__ float g_mu[BB*KCL*64];
__device__ float g_muacc[2*BB*KCL*64];
__device__ float g_m2[BB*KCL];
__device__ float g_logpi[BB*KCL];
__device__ float g_Nk[2*BB*KCL];
__device__ float g_bqkv[2*1536];
__device__ double g_rec;
__device__ double g_kl;
// bf16 GEMM operand buffers
__device__ bf16 g_Hb[NTOK*DD];
__device__ bf16 g_qkvb[NTOK*1536];
__device__ bf16 g_vtb[64*128*256];
__device__ bf16 g_ob[NTOK*DD];
__device__ bf16 g_hAb[NTOK*DD];
__device__ bf16 g_attb[64*SSQ*SSQ];
__device__ bf16 g_zb[NZ*64];
__device__ bf16 g_wqkv0[1536*512];
__device__ bf16 g_wo0[512*512];
__device__ bf16 g_wqkv1[1536*512];
__device__ bf16 g_wo1[512*512];
__device__ bf16 g_w1t[1024*64];
__device__ bf16 g_w2t[1024*1024];
__device__ bf16 g_w3t[512*1024];
__device__ bf16 g_d1[41943040];
__device__ bf16 g_d2[41943040];

__device__ __forceinline__ float warpRedSum(float v){
#pragma unroll
    for (int o = 16; o > 0; o >>= 1) v += __shfl_xor_sync(0xffffffffu, v, o);
    return v;
}
__device__ __forceinline__ float warpRedMax(float v){
#pragma unroll
    for (int o = 16; o > 0; o >>= 1) v = fmaxf(v, __shfl_xor_sync(0xffffffffu, v, o));
    return v;
}
__device__ __forceinline__ uint32_t smem_u32(const void* p){
    uint32_t a;
    asm("{ .reg .u64 t; cvta.to.shared.u64 t, %1; cvt.u32.u64 %0, t; }" : "=r"(a) : "l"(p));
    return a;
}
__device__ __forceinline__ void ldsm4(uint32_t* r, uint32_t addr){
    asm volatile("ldmatrix.sync.aligned.m8n8.x4.shared.b16 {%0,%1,%2,%3}, [%4];"
        : "=r"(r[0]), "=r"(r[1]), "=r"(r[2]), "=r"(r[3]) : "r"(addr));
}
__device__ __forceinline__ void mma16(float* d, const uint32_t* a, const uint32_t* b){
    asm volatile(
        "mma.sync.aligned.m16n8k16.row.col.f32.bf16.bf16.f32 "
        "{%0,%1,%2,%3}, {%4,%5,%6,%7}, {%8,%9}, {%0,%1,%2,%3};"
        : "+f"(d[0]), "+f"(d[1]), "+f"(d[2]), "+f"(d[3])
        : "r"(a[0]), "r"(a[1]), "r"(a[2]), "r"(a[3]), "r"(b[0]), "r"(b[1]));
}
#define CP16(dst, src) \
    asm volatile("cp.async.cg.shared.global [%0], [%1], 16;" :: "r"(dst), "l"(src))
#define CP_COMMIT() asm volatile("cp.async.commit_group;" ::: "memory")

// =======================================================================
// BF16 tensor-core GEMM (see R10/R11).
// =======================================================================
__global__ __launch_bounds__(256, 2) void gemm_mma_kernel(
    const bf16* __restrict__ A, int lda, long long sAb, long long sAh,
    const bf16* __restrict__ B, int ldb, long long sBb, long long sBh,
    float* __restrict__ C, int ldc, long long sCb, long long sCh,
    bf16* __restrict__ Cb, int c32lim,
    int K,
    const float* __restrict__ bias,
    const float* __restrict__ residual, int ldres, long long sRb, long long sRh,
    float scale, int doRelu, int lossMode,
    const float* __restrict__ lossH)
{
    extern __shared__ __align__(16) char smem[];
    const int tid = threadIdx.x;
    const int wid = tid >> 5, lane = tid & 31;

    const int zb = blockIdx.z >> 2, zh = blockIdx.z & 3;
    A += (long long)zb * sAb + (long long)zh * sAh;
    B += (long long)zb * sBb + (long long)zh * sBh;
    if (C)        C        += (long long)zb * sCb + (long long)zh * sCh;
    if (Cb)       Cb       += (long long)zb * sCb + (long long)zh * sCh;
    if (residual) residual += (long long)zb * sRb + (long long)zh * sRh;

    const int m0 = blockIdx.y * 128, n0 = blockIdx.x * 128;
    const bool wr32 = (C != nullptr) && (n0 < c32lim);
    const int kTiles = K >> 6;
    const uint32_t smem0 = smem_u32(smem);

    const int srow = tid & 127;
    const bool isB = (tid >= 128);
    const bf16* gsrc = isB ? (B + (size_t)(n0 + srow) * ldb)
                           : (A + (size_t)(m0 + srow) * lda);
    const uint32_t sdst0 = smem0 + (isB ? 16384 : 0) + srow * 128;
    const int rx = srow & 7;

    const int pstages = kTiles < 2 ? kTiles : 2;
    for (int c = 0; c < pstages; c++){
        const bf16* gs = gsrc + c * 64;
        const uint32_t sd = sdst0 + c * 32768;
#pragma unroll
        for (int j = 0; j < 8; j++)
            CP16(sd + ((j ^ rx) << 4), gs + j * 8);
        CP_COMMIT();
    }

    float acc[2][8][4];
#pragma unroll
    for (int i = 0; i < 2; i++)
#pragma unroll
        for (int j = 0; j < 8; j++)
#pragma unroll
            for (int q = 0; q < 4; q++) acc[i][j][q] = 0.f;

    const int wm = (wid & 3) * 32;
    const int wn = (wid >> 2) * 64;
    const int rr = lane & 7;
    const int qm = lane >> 3;
    const int qlow = qm & 1, qhigh = qm >> 1;
    uint32_t rowbaseA[2];
#pragma unroll
    for (int mt = 0; mt < 2; mt++)
        rowbaseA[mt] = (uint32_t)((wm + mt*16 + rr + 8*qlow) * 128);
    uint32_t rowbaseB[4];
#pragma unroll
    for (int p = 0; p < 4; p++)
        rowbaseB[p] = (uint32_t)(16384 + (wn + (2*p + qhigh)*8 + rr) * 128);

    for (int c = 0; c < kTiles; c++){
        if (c + 1 < kTiles) asm volatile("cp.async.wait_group 1;" ::: "memory");
        else                asm volatile("cp.async.wait_group 0;" ::: "memory");
        __syncthreads();

        if (c + 2 < kTiles){
            const bf16* gs = gsrc + (c + 2) * 64;
            const uint32_t sd = sdst0 + ((c + 2) % 3) * 32768;
#pragma unroll
            for (int j = 0; j < 8; j++)
                CP16(sd + ((j ^ rx) << 4), gs + j * 8);
            CP_COMMIT();
        }

        const uint32_t st = smem0 + (c % 3) * 32768;
#pragma unroll
        for (int t = 0; t < 4; t++){
            const uint32_t offA = (uint32_t)(((2*t + qhigh) ^ rr) << 4);
            const uint32_t offB = (uint32_t)(((2*t + qlow) ^ rr) << 4);
            uint32_t a[2][4], bb[4][4];
            ldsm4(a[0], st + rowbaseA[0] + offA);
            ldsm4(a[1], st + rowbaseA[1] + offA);
#pragma unroll
            for (int p = 0; p < 4; p++)
                ldsm4(bb[p], st + rowbaseB[p] + offB);
#pragma unroll
            for (int p = 0; p < 4; p++){
                mma16(acc[0][2*p+0], a[0], &bb[p][0]);
                mma16(acc[1][2*p+0], a[1], &bb[p][0]);
                mma16(acc[0][2*p+1], a[0], &bb[p][2]);
                mma16(acc[1][2*p+1], a[1], &bb[p][2]);
            }
        }
    }

    if (!lossMode){
#pragma unroll
        for (int mt = 0; mt < 2; mt++){
#pragma unroll
            for (int half = 0; half < 2; half++){
                int r = m0 + wm + mt*16 + (lane >> 2) + half*8;
                float* crow = wr32 ? (C + (size_t)r * ldc) : nullptr;
                bf16* crowb = Cb ? (Cb + (size_t)r * ldc) : nullptr;
                const float* rrow = residual ? (residual + (size_t)r * ldres) : nullptr;
#pragma unroll
                for (int nt = 0; nt < 8; nt++){
                    int col = n0 + wn + nt*8 + (lane & 3)*2;
                    float f0 = acc[mt][nt][half*2 + 0] * scale;
                    float f1 = acc[mt][nt][half*2 + 1] * scale;
                    if (bias){ f0 += bias[col]; f1 += bias[col + 1]; }
                    if (doRelu){ f0 = fmaxf(f0, 0.f); f1 = fmaxf(f1, 0.f); }
                    if (rrow){
                        float2 rv = *(const float2*)(rrow + col);
                        f0 += rv.x; f1 += rv.y;
                    }
                    if (crow)  *(float2*)(crow + col) = make_float2(f0, f1);
                    if (crowb) *(bf162*)(crowb + col) = __floats2bfloat162_rn(f0, f1);
                }
            }
        }
    } else {
        double lsum = 0.0;
#pragma unroll
        for (int mt = 0; mt < 2; mt++){
#pragma unroll
            for (int half = 0; half < 2; half++){
                int r = m0 + wm + mt*16 + (lane >> 2) + half*8;
                const float* hrow = lossH + (size_t)(r / 10) * 512;
#pragma unroll
                for (int nt = 0; nt < 8; nt++){
                    int col = n0 + wn + nt*8 + (lane & 3)*2;
                    float f0 = fmaxf(acc[mt][nt][half*2 + 0] + bias[col], 0.f);
                    float f1 = fmaxf(acc[mt][nt][half*2 + 1] + bias[col + 1], 0.f);
                    float d0 = f0 - hrow[col];
                    float d1 = f1 - hrow[col + 1];
                    lsum += (double)d0 * d0 + (double)d1 * d1;
                }
            }
        }
#pragma unroll
        for (int o = 16; o > 0; o >>= 1) lsum += __shfl_xor_sync(0xffffffffu, lsum, o);
        __shared__ double ds[8];
        if (lane == 0) ds[wid] = lsum;
        __syncthreads();
        if (tid == 0){
            double t = 0;
            for (int i = 0; i < 8; i++) t += ds[i];
            atomicAdd(&g_rec, t);
        }
    }
}

__global__ void transpose_w_kernel(const float* __restrict__ W,
                                   bf16* __restrict__ out, int K, int N)
{
    __shared__ float t[32][33];
    const int k0 = blockIdx.y * 32, n0 = blockIdx.x * 32;
    for (int i = threadIdx.y; i < 32; i += 8)
        t[i][threadIdx.x] = W[(size_t)(k0 + i) * N + n0 + threadIdx.x];
    __syncthreads();
    for (int i = threadIdx.y; i < 32; i += 8)
        out[(size_t)(n0 + i) * K + k0 + threadIdx.x] = __float2bfloat16(t[threadIdx.x][i]);
}

__global__ void transpose_qkv_kernel(const float* __restrict__ Wq,
                                     const float* __restrict__ Wk,
                                     const float* __restrict__ Wv,
                                     bf16* __restrict__ out)
{
    __shared__ float t[32][33];
    const float* W = blockIdx.z == 0 ? Wq : (blockIdx.z == 1 ? Wk : Wv);
    const int k0 = blockIdx.y * 32, n0 = blockIdx.x * 32;
    for (int i = threadIdx.y; i < 32; i += 8)
        t[i][threadIdx.x] = W[(size_t)(k0 + i) * 512 + n0 + threadIdx.x];
    __syncthreads();
    const int nout = blockIdx.z * 512 + n0;
    for (int i = threadIdx.y; i < 32; i += 8)
        out[(size_t)(nout + i) * 512 + k0 + threadIdx.x] = __float2bfloat16(t[threadIdx.x][i]);
}

// Fused prologue: accumulator zeroing + bf16 copy of H + qkv bias packing.
__global__ void prologue_kernel(const float* __restrict__ H,
                                const float* __restrict__ bq,
                                const float* __restrict__ bk,
                                const float* __restrict__ bv)
{
    int i = blockIdx.x * 256 + threadIdx.x;
    if (i == 0){ g_rec = 0.0; g_kl = 0.0; }
    float4 v = *(const float4*)(H + i * 4);
    *(bf162*)(g_Hb + i * 4)     = __floats2bfloat162_rn(v.x, v.y);
    *(bf162*)(g_Hb + i * 4 + 2) = __floats2bfloat162_rn(v.z, v.w);
    if (i < 2*1536){
        int layer = i / 1536, col = i % 1536;
        const float* src = col < 512 ? bq : (col < 1024 ? bk : bv);
        g_bqkv[i] = src[layer*512 + (col & 511)];
    }
}

__global__ void transpose_v_kernel()
{
    __shared__ float t[32][33];
    const int bh = blockIdx.z, b = bh >> 2, h = bh & 3;
    const int k0 = blockIdx.x * 32;
    const int n0 = blockIdx.y * 32;
    for (int i = threadIdx.y; i < 32; i += 8)
        t[i][threadIdx.x] = __bfloat162float(
            g_qkvb[((size_t)b * 256 + k0 + i) * 1536 + 1024 + h * 128 + n0 + threadIdx.x]);
    __syncthreads();
    for (int i = threadIdx.y; i < 32; i += 8)
        g_vtb[((size_t)bh * 128 + n0 + i) * 256 + k0 + threadIdx.x] = __float2bfloat16(t[threadIdx.x][i]);
}

// =======================================================================
// Fused stats GEMM (32x128 tile, fp32 SIMT) + z/logqz computation.
// =======================================================================
__global__ __launch_bounds__(256) void stats_z_kernel(
    const float* __restrict__ A, const float* __restrict__ W,
    const float* __restrict__ bias, const float* __restrict__ eps)
{
    __shared__ float As[8][32];
    __shared__ float Bs[8][128];
    __shared__ float sst[32][132];
    const int tid = threadIdx.x;
    const int m0 = blockIdx.x * 32;
    const int tx = tid & 15, ty = tid >> 4;

    float acc[2][8];
#pragma unroll
    for (int i = 0; i < 2; i++)
#pragma unroll
        for (int j = 0; j < 8; j++) acc[i][j] = 0.f;

    for (int k0 = 0; k0 < 512; k0 += 8) {
        if (tid < 64) {
            int r = tid >> 1, cq = (tid & 1) * 4;
            float4 v = *(const float4*)(A + (size_t)(m0 + r) * 512 + k0 + cq);
            As[cq+0][r] = v.x; As[cq+1][r] = v.y;
            As[cq+2][r] = v.z; As[cq+3][r] = v.w;
        }
        {
            int r = tid >> 5, col = (tid & 31) * 4;
            *(float4*)&Bs[r][col] = *(const float4*)(W + (size_t)(k0 + r) * 128 + col);
        }
        __syncthreads();
#pragma unroll
        for (int kk = 0; kk < 8; kk++) {
            float fa0 = As[kk][2*ty], fa1 = As[kk][2*ty + 1];
            float fb[8];
            *(float4*)&fb[0] = *(const float4*)&Bs[kk][tx*8];
            *(float4*)&fb[4] = *(const float4*)&Bs[kk][tx*8 + 4];
#pragma unroll
            for (int j = 0; j < 8; j++){
                acc[0][j] = fmaf(fa0, fb[j], acc[0][j]);
                acc[1][j] = fmaf(fa1, fb[j], acc[1][j]);
            }
        }
        __syncthreads();
    }

    float bl[8];
#pragma unroll
    for (int j = 0; j < 8; j++) bl[j] = bias[tx*8 + j];
#pragma unroll
    for (int i = 0; i < 2; i++)
#pragma unroll
        for (int j = 0; j < 8; j++)
            sst[2*ty + i][tx*8 + j] = acc[i][j] + bl[j];
    __syncthreads();

    const int lane = tid & 31, w = tid >> 5;
    for (int tt = 0; tt < 4; tt++){
        const int t = w*4 + tt;
        const int bs = m0 + t;
        const float mean0 = sst[t][lane];
        const float mean1 = sst[t][32 + lane];
        const float lv0   = sst[t][64 + lane];
        const float lv1   = sst[t][96 + lane];
        const float sd0 = expf(0.5f * lv0), sd1 = expf(0.5f * lv1);
        const float lvs = lv0 + lv1;
        for (int m = 0; m < 10; m++) {
            size_t off = ((size_t)bs*10 + m)*64;
            float e0 = eps[off + lane], e1 = eps[off + 32 + lane];
            float z0 = mean0 + e0 * sd0, z1 = mean1 + e1 * sd1;
            g_z[off + lane] = z0;        g_z[off + 32 + lane] = z1;
            g_zb[off + lane] = __float2bfloat16(z0);
            g_zb[off + 32 + lane] = __float2bfloat16(z1);
            float qv = warpRedSum(lvs + e0*e0 + e1*e1);
            if (lane == 0) g_logqz[(size_t)bs*10 + m] = -0.5f*qv + 64.f*LOG_NORM_F;
        }
    }
}

__global__ __launch_bounds__(256) void softmax_kernel()
{
    const int lane = threadIdx.x & 31;
    const int row = blockIdx.x * 8 + (threadIdx.x >> 5);
    const float* p = g_att + (size_t)row * SSQ;
    bf16* po = g_attb + (size_t)row * SSQ;
    float v[8];
    float mx = -1e30f;
#pragma unroll
    for (int j = 0; j < 8; j++){
        v[j] = p[lane + 32*j];
        mx = fmaxf(mx, v[j]);
    }
    mx = warpRedMax(mx);
    float s = 0.f;
#pragma unroll
    for (int j = 0; j < 8; j++){
        v[j] = expf(v[j] - mx);
        s += v[j];
    }
    s = warpRedSum(s);
#pragma unroll
    for (int j = 0; j < 8; j++)
        po[lane + 32*j] = __float2bfloat16(v[j] / s);
}

__global__ void init_mu_kernel(const int* __restrict__ idx)
{
    const int b = blockIdx.x, k = blockIdx.y, l = threadIdx.x;
    const int lane = l & 31, w = l >> 5;
    const int n = idx[b*KCL + k];
    float v = g_z[((size_t)b*NPB + n)*64 + l];
    g_mu[((size_t)b*KCL + k)*64 + l] = v;
    float s = warpRedSum(v*v);
    __shared__ float sm[2];
    if (lane == 0) sm[w] = s;
    __syncthreads();
    if (l == 0) {
        g_m2[b*KCL + k] = sm[0] + sm[1];
        g_logpi[b*KCL + k] = -2.9957322735539909f;
    }
}

__global__ void zero_em_kernel()
{
    int i = blockIdx.x * 256 + threadIdx.x;
    if (i < 2*BB*KCL) g_Nk[i] = 0.f;
    if (i < 2*BB*KCL*64) g_muacc[i] = 0.f;
}

__global__ __launch_bounds__(256) void em_step_kernel(int parity)
{
    const int b = blockIdx.y;
    const int tid = threadIdx.x, lane = tid & 31, w = tid >> 5;
    __shared__ float mus[KCL*64];
    __shared__ float sc[KCL];
    __shared__ float nkacc[KCL];
    __shared__ float zt[64*65];
    __shared__ float pt[64*21];

    const int n0 = blockIdx.x * 64;
    for (int i = tid; i < KCL*64; i += 256) mus[i] = g_mu[(size_t)b*KCL*64 + i];
    if (tid < KCL) { sc[tid] = -0.5f*g_m2[b*KCL+tid] + g_logpi[b*KCL+tid]; nkacc[tid] = 0.f; }
    for (int i = tid; i < 64*64; i += 256)
        zt[(i >> 6)*65 + (i & 63)] = g_z[((size_t)b*NPB + n0)*64 + i];

    {
        const int op = parity ^ 1;
        if (tid < 32)
            g_muacc[((size_t)op*BB + b)*KCL*64 + blockIdx.x*32 + tid] = 0.f;
        if (blockIdx.x == 0 && tid < KCL)
            g_Nk[(op*BB + b)*KCL + tid] = 0.f;
    }
    __syncthreads();

    float nkloc = 0.f;
    const int nb = w * 8;
    for (int t = 0; t < 8; t++) {
        const int n = nb + t;
        float z0 = zt[n*65 + lane], z1 = zt[n*65 + 32 + lane];
        float mx = -1e30f, s = 0.f, myll = 0.f;
#pragma unroll
        for (int k2 = 0; k2 < KCL; k2++) {
            float p = z0*mus[k2*64+lane] + z1*mus[k2*64+32+lane];
            p = warpRedSum(p) + sc[k2];
            if (lane == k2) myll = p;
            float nm = fmaxf(mx, p);
            s = s*expf(mx - nm) + expf(p - nm);
            mx = nm;
        }
        if (lane < KCL) {
            float pk = expf(myll - mx) / s;
            pt[n*21 + lane] = pk;
            nkloc += pk;
        }
    }
    if (lane < KCL) atomicAdd(&nkacc[lane], nkloc);
    __syncthreads();

    {
        const int l = tid & 63, kq = tid >> 6;
        float a0=0.f, a1=0.f, a2=0.f, a3=0.f, a4=0.f;
#pragma unroll 4
        for (int nn = 0; nn < 64; nn++){
            float zv = zt[nn*65 + l];
            const float* pr = pt + nn*21 + kq*5;
            a0 = fmaf(pr[0], zv, a0);
            a1 = fmaf(pr[1], zv, a1);
            a2 = fmaf(pr[2], zv, a2);
            a3 = fmaf(pr[3], zv, a3);
            a4 = fmaf(pr[4], zv, a4);
        }
        float* dst = g_muacc + (((size_t)parity*BB + b)*KCL + kq*5)*64 + l;
        atomicAdd(dst,       a0);
        atomicAdd(dst + 64,  a1);
        atomicAdd(dst + 128, a2);
        atomicAdd(dst + 192, a3);
        atomicAdd(dst + 256, a4);
    }
    if (tid < KCL) atomicAdd(&g_Nk[(parity*BB + b)*KCL + tid], nkacc[tid]);
}

__global__ void em_fin_kernel(int parity)
{
    const int k = blockIdx.x, b = blockIdx.y, l = threadIdx.x;
    const int lane = l & 31, w = l >> 5;
    const float* Nk = g_Nk + (parity*BB + b)*KCL;
    float nk = Nk[k];
    float m = g_muacc[(((size_t)parity*BB + b)*KCL + k)*64 + l] / nk;
    g_mu[((size_t)b*KCL + k)*64 + l] = m;
    float s = warpRedSum(m*m);
    __shared__ float sm[2];
    if (lane == 0) sm[w] = s;
    __syncthreads();
    if (l == 0) {
        g_m2[b*KCL + k] = sm[0] + sm[1];
        float tot = 0.f;
        for (int j = 0; j < KCL; j++) tot += Nk[j];
        g_logpi[b*KCL + k] = logf(nk / tot);
    }
}

__global__ __launch_bounds__(256) void kl_kernel()
{
    const int b = blockIdx.y;
    const int tid = threadIdx.x, lane = tid & 31, w = tid >> 5;
    __shared__ float mus[KCL*64];
    __shared__ float sc[KCL];
    for (int i = tid; i < KCL*64; i += 256) mus[i] = g_mu[(size_t)b*KCL*64 + i];
    if (tid < KCL) sc[tid] = -0.5f*g_m2[b*KCL+tid] + g_logpi[b*KCL+tid];
    __syncthreads();

    double loc = 0.0;
    const int nbase = blockIdx.x*64 + w*8;
    for (int t = 0; t < 8; t++) {
        int n = nbase + t;
        const float* zp = g_z + ((size_t)b*NPB + n)*64;
        float z0 = zp[lane], z1 = zp[lane+32];
        float sq = warpRedSum(z0*z0 + z1*z1);
        float mx = -1e30f, s = 0.f;
#pragma unroll
        for (int k2 = 0; k2 < KCL; k2++) {
            float p = z0*mus[k2*64+lane] + z1*mus[k2*64+32+lane];
            p = warpRedSum(p) + sc[k2];
            float nm = fmaxf(mx, p);
            s = s*expf(mx - nm) + expf(p - nm);
            mx = nm;
        }
        float lpz = mx + logf(s) - 0.5f*sq + 64.f*LOG_NORM_F;
        if (lane == 0) loc += (double)(g_logqz[(size_t)b*NPB + n] - lpz);
    }
    __shared__ double dacc[8];
    if (lane == 0) dacc[w] = loc;
    __syncthreads();
    if (tid == 0) {
        double t = 0;
        for (int i = 0; i < 8; i++) t += dacc[i];
        atomicAdd(&g_kl, t);
    }
}

__global__ void finalize_kernel(float* __restrict__ out)
{
    out[0] = (float)(g_rec / 40960.0);
    out[1] = (float)(g_kl / 40960.0);
}

static void* symaddr(const void* s)
{
    void* p = nullptr;
    cudaGetSymbolAddress(&p, s);
    return p;
}

#define GEMM_SMEM 98304
#define BIG32 (1 << 30)

extern "C" void kernel_launch(void* const* d_in, const int* in_sizes, int n_in,
                              void* d_out, int out_size)
{
    const float *H, *eps, *wq, *bq, *wk, *bk, *wv, *bv, *wo, *bo, *wz, *bz;
    const float *w1, *b1, *w2, *b2, *w3, *b3;
    const int* init_idx;

    if (n_in >= 3 && in_sizes[2] == 320) {
        H = (const float*)d_in[0];  eps = (const float*)d_in[1]; init_idx = (const int*)d_in[2];
        wq = (const float*)d_in[3]; bq = (const float*)d_in[4];
        wk = (const float*)d_in[5]; bk = (const float*)d_in[6];
        wv = (const float*)d_in[7]; bv = (const float*)d_in[8];
        wo = (const float*)d_in[9]; bo = (const float*)d_in[10];
        wz = (const float*)d_in[11]; bz = (const float*)d_in[12];
        w1 = (const float*)d_in[13]; b1 = (const float*)d_in[14];
        w2 = (const float*)d_in[15]; b2 = (const float*)d_in[16];
        w3 = (const float*)d_in[17]; b3 = (const float*)d_in[18];
    } else {
        H = (const float*)d_in[0];  eps = (const float*)d_in[1];
        wq = (const float*)d_in[2]; bq = (const float*)d_in[3];
        wk = (const float*)d_in[4]; bk = (const float*)d_in[5];
        wv = (const float*)d_in[6]; bv = (const float*)d_in[7];
        wo = (const float*)d_in[8]; bo = (const float*)d_in[9];
        wz = (const float*)d_in[10]; bz = (const float*)d_in[11];
        w1 = (const float*)d_in[12]; b1 = (const float*)d_in[13];
        w2 = (const float*)d_in[14]; b2 = (const float*)d_in[15];
        w3 = (const float*)d_in[16]; b3 = (const float*)d_in[17];
        init_idx = (const int*)d_in[18];
    }

    cudaFuncSetAttribute(gemm_mma_kernel,
                         cudaFuncAttributeMaxDynamicSharedMemorySize, GEMM_SMEM);

    static cudaStream_t s2 = nullptr;
    static cudaEvent_t evStart = nullptr, evW0 = nullptr, evW = nullptr,
                       evFork = nullptr, evJoin = nullptr;
    static cudaEvent_t evQ[2] = {nullptr, nullptr}, evV[2] = {nullptr, nullptr};
    if (s2 == nullptr) {
        cudaStreamCreateWithFlags(&s2, cudaStreamNonBlocking);
        cudaEventCreateWithFlags(&evStart, cudaEventDisableTiming);
        cudaEventCreateWithFlags(&evW0, cudaEventDisableTiming);
        cudaEventCreateWithFlags(&evW, cudaEventDisableTiming);
        cudaEventCreateWithFlags(&evFork, cudaEventDisableTiming);
        cudaEventCreateWithFlags(&evJoin, cudaEventDisableTiming);
        for (int i = 0; i < 2; i++){
            cudaEventCreateWithFlags(&evQ[i], cudaEventDisableTiming);
            cudaEventCreateWithFlags(&evV[i], cudaEventDisableTiming);
        }
    }

    bf16* Hb    = (bf16*)symaddr(g_Hb);
    float* qkv  = (float*)symaddr(g_qkv);
    bf16* qkvb  = (bf16*)symaddr(g_qkvb);
    float* op   = (float*)symaddr(g_o);
    bf16* ob    = (bf16*)symaddr(g_ob);
    bf16* hAb   = (bf16*)symaddr(g_hAb);
    float* hB   = (float*)symaddr(g_hB);
    float* attp = (float*)symaddr(g_att);
    bf16* attb  = (bf16*)symaddr(g_attb);
    bf16* zbp   = (bf16*)symaddr(g_zb);
    bf16* vtb   = (bf16*)symaddr(g_vtb);
    bf16* wqkv0 = (bf16*)symaddr(g_wqkv0);
    bf16* wo0t  = (bf16*)symaddr(g_wo0);
    bf16* wqkv1 = (bf16*)symaddr(g_wqkv1);
    bf16* wo1t  = (bf16*)symaddr(g_wo1);
    bf16* w1t   = (bf16*)symaddr(g_w1t);
    bf16* w2t   = (bf16*)symaddr(g_w2t);
    bf16* w3t   = (bf16*)symaddr(g_w3t);
    float* bqkv = (float*)symaddr(g_bqkv);
    bf16* d1b   = (bf16*)symaddr(g_d1);
    bf16* d2b   = (bf16*)symaddr(g_d2);

    // fused prologue on stream 0 + fork s2 into the capture
    prologue_kernel<<<2048, 256>>>(H, bq, bk, bv);
    cudaEventRecord(evStart, 0);
    cudaStreamWaitEvent(s2, evStart, 0);

    // s2: ALL weight transposes. wqkv0 first (needed earliest).
    transpose_qkv_kernel<<<dim3(16,16,3), dim3(32,8), 0, s2>>>(wq, wk, wv, wqkv0);
    cudaEventRecord(evW0, s2);
    transpose_w_kernel<<<dim3(16,16), dim3(32,8), 0, s2>>>(wo, wo0t, 512, 512);
    transpose_qkv_kernel<<<dim3(16,16,3), dim3(32,8), 0, s2>>>(wq + DD*DD, wk + DD*DD, wv + DD*DD, wqkv1);
    transpose_w_kernel<<<dim3(16,16), dim3(32,8), 0, s2>>>(wo + DD*DD, wo1t, 512, 512);
    transpose_w_kernel<<<dim3(32,2), dim3(32,8), 0, s2>>>(w1, w1t, 64, 1024);
    transpose_w_kernel<<<dim3(32,32), dim3(32,8), 0, s2>>>(w2, w2t, 1024, 1024);
    transpose_w_kernel<<<dim3(16,32), dim3(32,8), 0, s2>>>(w3, w3t, 1024, 512);
    cudaEventRecord(evW, s2);

    const float scl = 0.044194173824159216f;
    bf16* wqkvT[2] = { wqkv0, wqkv1 };
    bf16* woT[2]   = { wo0t, wo1t };
    const bf16* xinb = Hb;
    float* layer_out[2]  = { nullptr, hB };
    bf16* layer_outb[2]  = { hAb, nullptr };

    for (int i = 0; i < 2; i++) {
        const size_t boff = (size_t)i * DD;

        if (i == 0) cudaStreamWaitEvent(0, evW0, 0);   // wqkv0 ready

        // fused qkv: fp32 written only for q columns (residual)
        gemm_mma_kernel<<<dim3(12,32,1), 256, GEMM_SMEM>>>(
            xinb,512,0,0, wqkvT[i],512,0,0, qkv,1536,0,0, qkvb, 512, 512,
            bqkv + (size_t)i*1536, nullptr,0,0,0, 1.f,0,0,nullptr);

        // transpose_v on s2, overlapped with scores+softmax
        cudaEventRecord(evQ[i], 0);
        cudaStreamWaitEvent(s2, evQ[i], 0);
        transpose_v_kernel<<<dim3(8,4,64), dim3(32,8), 0, s2>>>();
        cudaEventRecord(evV[i], s2);

        // scores = q k^T / sqrt(D), K = 128 (head dim)
        gemm_mma_kernel<<<dim3(2,2,64), 256, GEMM_SMEM>>>(
            qkvb,1536,393216,128, qkvb+512,1536,393216,128,
            attp,256,262144,65536, nullptr, BIG32, 128,
            nullptr, nullptr,0,0,0, scl,0,0,nullptr);
        softmax_kernel<<<64*SSQ/8, 256>>>();

        // o = q + att @ v
        cudaStreamWaitEvent(0, evV[i], 0);
        gemm_mma_kernel<<<dim3(1,2,64), 256, GEMM_SMEM>>>(
            attb,256,262144,65536, vtb,256,131072,32768,
            op,512,131072,128, ob, BIG32, 256,
            nullptr, qkv,1536,393216,128, 1.f,0,0,nullptr);

        // out = o + relu(ob @ wo + bo)
        if (i == 0) cudaStreamWaitEvent(0, evW, 0);    // remaining transposes ready
        gemm_mma_kernel<<<dim3(4,32,1), 256, GEMM_SMEM>>>(
            ob,512,0,0, woT[i],512,0,0, layer_out[i],512,0,0,
            layer_outb[i], BIG32, 512, bo+boff, op,512,0,0, 1.f,1,0,nullptr);
        xinb = layer_outb[i];
    }

    // fused stats + z (+ logqz), grid 128 x 32-token tiles
    stats_z_kernel<<<128, 256>>>(hB, wz, bz, eps);

    // ---- fork: EM + KL on s2, decoder on default ----
    cudaEventRecord(evFork, 0);
    cudaStreamWaitEvent(s2, evFork, 0);

    init_mu_kernel<<<dim3(BB, KCL), 64, 0, s2>>>(init_idx);
    zero_em_kernel<<<161, 256, 0, s2>>>();
    for (int it = 0; it < 5; it++) {
        em_step_kernel<<<dim3(40, BB), 256, 0, s2>>>(it & 1);
        em_fin_kernel<<<dim3(KCL, BB), 64, 0, s2>>>(it & 1);
    }
    kl_kernel<<<dim3(40, BB), 256, 0, s2>>>();
    cudaEventRecord(evJoin, s2);

    // decoder on default stream
    gemm_mma_kernel<<<dim3(8,320,1), 256, GEMM_SMEM>>>(
        zbp,64,0,0, w1t,64,0,0, nullptr,1024,0,0, d1b, BIG32,
        64, b1, nullptr,0,0,0, 1.f,1,0,nullptr);
    gemm_mma_kernel<<<dim3(8,320,1), 256, GEMM_SMEM>>>(
        d1b,1024,0,0, w2t,1024,0,0, nullptr,1024,0,0, d2b, BIG32,
        1024, b2, nullptr,0,0,0, 1.f,1,0,nullptr);
    gemm_mma_kernel<<<dim3(4,320,1), 256, GEMM_SMEM>>>(
        d2b,1024,0,0, w3t,1024,0,0, nullptr,512,0,0, nullptr, BIG32,
        1024, b3, nullptr,0,0,0, 1.f,0,1,H);

    cudaStreamWaitEvent(0, evJoin, 0);
    finalize_kernel<<<1, 1>>>((float*)d_out);
    (void)in_sizes; (void)n_in; (void)out_size;
}